// round 1
// baseline (speedup 1.0000x reference)
#include <cuda_runtime.h>
#include <math.h>

// WindowAttention fused kernel (fp32 baseline).
// B=4096 windows, L=49 tokens, C=128, 4 heads, head_dim=32.
// One CTA per window. Everything (x tile, q/k/v, weight tiles) staged in smem.
//
// Inputs (metadata order):
//  0: x        [4096, 49, 128] f32
//  1: W_qkv    [128, 384]      f32
//  2: b_qkv    [384]           f32
//  3: W_proj   [128, 128]      f32
//  4: b_proj   [128]           f32
//  5: rel_pos_h[13, 32]        f32
//  6: rel_pos_w[13, 32]        f32
// out: [4096, 49, 128] f32

#define NWIN 4096
#define LL   49
#define CC   128
#define NH   4
#define HD   32
#define QK_SCALE 0.17677669529663687f   // 32^-0.5

// smem layout in floats
#define OFF_X 0                 // xs [49][128] (later reused as ao [49][132])
#define OFF_Q 6468              // q  [4][49][33]  (padded stride 33: conflict-free per-lane reads)
#define OFF_K 12936             // k  [4][49][32]
#define OFF_V 19208             // v  [4][49][32]
#define OFF_S 25480             // scratch: weight tile [128][128] / rel tables
#define SMEM_FLOATS (OFF_S + 128*128)
#define SMEM_BYTES  (SMEM_FLOATS * 4)

extern __shared__ float sm[];

__global__ void __launch_bounds__(256, 1)
win_attn_kernel(const float* __restrict__ x,
                const float* __restrict__ Wqkv,
                const float* __restrict__ bqkv,
                const float* __restrict__ Wproj,
                const float* __restrict__ bproj,
                const float* __restrict__ relh,
                const float* __restrict__ relw,
                float* __restrict__ out)
{
    const int b = blockIdx.x;
    const int t = threadIdx.x;

    float* xs = sm + OFF_X;
    float* qs = sm + OFF_Q;
    float* ks = sm + OFF_K;
    float* vs = sm + OFF_V;
    float* wt = sm + OFF_S;
    float4* wt4 = reinterpret_cast<float4*>(wt);

    // ---------------- load x tile ----------------
    {
        const float4* xg = reinterpret_cast<const float4*>(x + (size_t)b * LL * CC);
        float4* xs4 = reinterpret_cast<float4*>(xs);
        #pragma unroll
        for (int i = t; i < LL * CC / 4; i += 256) xs4[i] = xg[i];
    }
    __syncthreads();

    const int tr = t >> 5;   // warp id: row group (rows tr, tr+8, ..., tr+48)
    const int tg = t & 31;   // lane id: 4-column group within 128-wide tile

    // clamped row pointers (row 48 duplicated for guarded slots; stores are guarded)
    const float* xrow[7];
    #pragma unroll
    for (int r = 0; r < 7; r++) {
        int l = tr + 8 * r; if (l > 48) l = 48;
        xrow[r] = xs + l * CC;
    }

    // ---------------- QKV GEMM: [49x128] @ [128x384] ----------------
    // 3 passes of 128 output columns; weight tile staged in smem.
    for (int jt = 0; jt < 3; jt++) {
        {
            const float* wg = Wqkv + jt * 128;
            for (int i = t; i < 128 * 32; i += 256) {
                int c = i >> 5, g = i & 31;
                wt4[i] = *reinterpret_cast<const float4*>(wg + c * 384 + g * 4);
            }
        }
        __syncthreads();

        float acc[7][4];
        #pragma unroll
        for (int r = 0; r < 7; r++)
            #pragma unroll
            for (int q = 0; q < 4; q++) acc[r][q] = 0.f;

        #pragma unroll 4
        for (int c = 0; c < 128; c++) {
            float4 wv = wt4[c * 32 + tg];
            #pragma unroll
            for (int r = 0; r < 7; r++) {
                float xv = xrow[r][c];          // warp-broadcast LDS
                acc[r][0] += xv * wv.x;
                acc[r][1] += xv * wv.y;
                acc[r][2] += xv * wv.z;
                acc[r][3] += xv * wv.w;
            }
        }

        // scatter-store into q/k/v with the reference's interleaved column map:
        // j -> (kk = j%3, f = (j/3)%4, d = j/12)
        #pragma unroll
        for (int r = 0; r < 7; r++) {
            int l = tr + 8 * r;
            if (l > 48) continue;
            #pragma unroll
            for (int q = 0; q < 4; q++) {
                int j = jt * 128 + tg * 4 + q;
                float v = acc[r][q] + bqkv[j];
                int kk = j % 3;
                int f  = (j / 3) & 3;
                int d  = j / 12;
                if (kk == 0)      qs[(f * 49 + l) * 33 + d] = v;
                else if (kk == 1) ks[(f * 49 + l) * 32 + d] = v;
                else              vs[(f * 49 + l) * 32 + d] = v;
            }
        }
        __syncthreads();
    }

    // ---------------- rel-pos tables into scratch ----------------
    float* Rh = wt;             // [13][33] padded
    float* Rw = wt + 13 * 33;   // [13][33]
    for (int i = t; i < 13 * 32; i += 256) {
        int r = i >> 5, c = i & 31;
        Rh[r * 33 + c] = relh[i];
        Rw[r * 33 + c] = relw[i];
    }
    __syncthreads();

    // ---------------- attention: one lane per (head, row) ----------------
    // warp w: head f = w/2; half = w&1; lane handles row l = half*32 + lane.
    {
        const int f    = tr >> 1;
        const int half = tr & 1;
        const int l    = half * 32 + tg;
        const bool active = (l < 49);
        const int li   = active ? l : 0;

        // q row -> registers (stride-33 layout: conflict-free across lanes)
        float qreg[32];
        const float* qrow = qs + (f * 49 + li) * 33;
        #pragma unroll
        for (int d = 0; d < 32; d++) qreg[d] = qrow[d];

        // decomposed rel-pos bias terms for this row
        const int hi = li / 7, wi = li % 7;
        float hb[7], wb[7];
        #pragma unroll
        for (int kk = 0; kk < 7; kk++) {
            const float* rh = Rh + (hi - kk + 6) * 33;
            const float* rw = Rw + (wi - kk + 6) * 33;
            float a = 0.f, bb = 0.f;
            #pragma unroll
            for (int d = 0; d < 32; d++) {
                a  += qreg[d] * rh[d];
                bb += qreg[d] * rw[d];
            }
            hb[kk] = a; wb[kk] = bb;
        }

        // logits p[49] = scale * q.k + hb[hj] + wb[wj]   (k rows: broadcast LDS.128)
        float p[49];
        const float* kh = ks + f * 49 * 32;
        {
            int j = 0;
            #pragma unroll
            for (int hj = 0; hj < 7; hj++) {
                #pragma unroll
                for (int wj = 0; wj < 7; wj++, j++) {
                    const float4* kr = reinterpret_cast<const float4*>(kh + j * 32);
                    float a = 0.f;
                    #pragma unroll
                    for (int g = 0; g < 8; g++) {
                        float4 kv = kr[g];
                        a += qreg[4*g+0] * kv.x + qreg[4*g+1] * kv.y
                           + qreg[4*g+2] * kv.z + qreg[4*g+3] * kv.w;
                    }
                    p[j] = a * QK_SCALE + hb[hj] + wb[wj];
                }
            }
        }

        // softmax (registers)
        float mx = -1e30f;
        #pragma unroll
        for (int j = 0; j < 49; j++) mx = fmaxf(mx, p[j]);
        float s = 0.f;
        #pragma unroll
        for (int j = 0; j < 49; j++) { p[j] = __expf(p[j] - mx); s += p[j]; }
        const float inv = 1.f / s;

        // P @ V (v rows: broadcast LDS.128), accumulate in registers
        float o[32];
        #pragma unroll
        for (int d = 0; d < 32; d++) o[d] = 0.f;
        const float* vh = vs + f * 49 * 32;
        #pragma unroll
        for (int j = 0; j < 49; j++) {
            float pj = p[j];
            const float4* vr = reinterpret_cast<const float4*>(vh + j * 32);
            #pragma unroll
            for (int g = 0; g < 8; g++) {
                float4 vv = vr[g];
                o[4*g+0] += pj * vv.x;
                o[4*g+1] += pj * vv.y;
                o[4*g+2] += pj * vv.z;
                o[4*g+3] += pj * vv.w;
            }
        }

        __syncthreads();   // everyone done with qkv reads before xs region is reused as ao

        // write attention output ao[l][f*32+d], stride 132 (reduced STS conflicts)
        if (active) {
            float* ao = xs;
            #pragma unroll
            for (int d = 0; d < 32; d++) ao[li * 132 + f * 32 + d] = o[d] * inv;
        }
    }
    __syncthreads();

    // ---------------- proj GEMM: [49x128] @ [128x128] + bias ----------------
    {
        for (int i = t; i < 128 * 32; i += 256) {
            int c = i >> 5, g = i & 31;
            wt4[i] = *reinterpret_cast<const float4*>(Wproj + c * 128 + g * 4);
        }
        __syncthreads();

        const float* aor[7];
        #pragma unroll
        for (int r = 0; r < 7; r++) {
            int l = tr + 8 * r; if (l > 48) l = 48;
            aor[r] = xs + l * 132;
        }

        float acc[7][4];
        #pragma unroll
        for (int r = 0; r < 7; r++)
            #pragma unroll
            for (int q = 0; q < 4; q++) acc[r][q] = 0.f;

        #pragma unroll 4
        for (int c = 0; c < 128; c++) {
            float4 wv = wt4[c * 32 + tg];
            #pragma unroll
            for (int r = 0; r < 7; r++) {
                float xv = aor[r][c];
                acc[r][0] += xv * wv.x;
                acc[r][1] += xv * wv.y;
                acc[r][2] += xv * wv.z;
                acc[r][3] += xv * wv.w;
            }
        }

        float4 bp = *reinterpret_cast<const float4*>(bproj + tg * 4);
        #pragma unroll
        for (int r = 0; r < 7; r++) {
            int l = tr + 8 * r;
            if (l > 48) continue;
            float4 o4;
            o4.x = acc[r][0] + bp.x;
            o4.y = acc[r][1] + bp.y;
            o4.z = acc[r][2] + bp.z;
            o4.w = acc[r][3] + bp.w;
            *reinterpret_cast<float4*>(out + ((size_t)b * 49 + l) * 128 + tg * 4) = o4;
        }
    }
}

extern "C" void kernel_launch(void* const* d_in, const int* in_sizes, int n_in,
                              void* d_out, int out_size)
{
    const float* x     = (const float*)d_in[0];
    const float* Wqkv  = (const float*)d_in[1];
    const float* bqkv  = (const float*)d_in[2];
    const float* Wproj = (const float*)d_in[3];
    const float* bproj = (const float*)d_in[4];
    const float* relh  = (const float*)d_in[5];
    const float* relw  = (const float*)d_in[6];
    float* out = (float*)d_out;

    cudaFuncSetAttribute(win_attn_kernel,
                         cudaFuncAttributeMaxDynamicSharedMemorySize, SMEM_BYTES);

    win_attn_kernel<<<NWIN, 256, SMEM_BYTES>>>(x, Wqkv, bqkv, Wproj, bproj,
                                               relh, relw, out);
}